// round 8
// baseline (speedup 1.0000x reference)
#include <cuda_runtime.h>
#include <cstdint>

// ---------------------------------------------------------------------------
// RSSM observe scan, GB300 — round 8.
//   k_pre  : unchanged (merged pre_inp + pre_obs).
//   k_rssm v6: 64 clusters x 2 CTAs x 640 threads. Each CTA is split into
//     TWO independent 320-thread row-groups (4 batch rows each). Groups never
//     sync with each other: named barriers within a group, per-group DSMEM
//     mbarriers for the cross-CTA dn/stat exchanges. Groups drift out of
//     phase and hide each other's barrier/L2 stalls.
// ---------------------------------------------------------------------------

#define Bc 512
#define Tc 64
#define Ec 1024
#define Ac 32
#define Sc 30
#define Dc 200
#define Hc 200
#define SSc 230
#define OUTC 380

typedef unsigned long long ull;

__device__ float g_pre_inp[Tc * Bc * Hc];
__device__ float g_pre_obs[Tc * Bc * Hc];

// ---- packed f32x2 helpers -------------------------------------------------
__device__ __forceinline__ ull pk2(float a, float b) {
    ull r; asm("mov.b64 %0, {%1, %2};" : "=l"(r) : "f"(a), "f"(b)); return r;
}
__device__ __forceinline__ ull dup2(float a) {
    ull r; asm("mov.b64 %0, {%1, %1};" : "=l"(r) : "f"(a)); return r;
}
__device__ __forceinline__ float2 up2(ull v) {
    float x, y; asm("mov.b64 {%0, %1}, %2;" : "=f"(x), "=f"(y) : "l"(v));
    return make_float2(x, y);
}
__device__ __forceinline__ void fma2(ull& acc, ull a, ull b) {
    asm("fma.rn.f32x2 %0, %1, %2, %0;" : "+l"(acc) : "l"(a), "l"(b));
}

__device__ __forceinline__ float sigm(float x) { return 1.0f / (1.0f + __expf(-x)); }
__device__ __forceinline__ float eluf(float x) { return x > 0.0f ? x : (__expf(x) - 1.0f); }
__device__ __forceinline__ float softplusf(float x) {
    return x > 15.0f ? x : log1pf(__expf(x));
}

// ---- cluster helpers --------------------------------------------------------
__device__ __forceinline__ uint32_t smem_u32(const void* p) {
    uint32_t a;
    asm("{ .reg .u64 t; cvta.to.shared.u64 t, %1; cvt.u32.u64 %0, t; }"
        : "=r"(a) : "l"(p));
    return a;
}
__device__ __forceinline__ void st_peer_u64(uint32_t laddr, uint32_t rank, ull v) {
    uint32_t ra;
    asm volatile("mapa.shared::cluster.u32 %0, %1, %2;" : "=r"(ra)
                 : "r"(laddr), "r"(rank));
    asm volatile("st.shared::cluster.u64 [%0], %1;" :: "r"(ra), "l"(v) : "memory");
}
__device__ __forceinline__ uint32_t ctarank() {
    uint32_t r; asm("mov.u32 %0, %%cluster_ctarank;" : "=r"(r)); return r;
}
__device__ __forceinline__ void mbar_init(uint32_t addr, uint32_t cnt) {
    asm volatile("mbarrier.init.shared.b64 [%0], %1;" :: "r"(addr), "r"(cnt)
                 : "memory");
}
__device__ __forceinline__ void mbar_arrive_peer(uint32_t laddr, uint32_t rank) {
    uint32_t ra;
    asm volatile("mapa.shared::cluster.u32 %0, %1, %2;" : "=r"(ra)
                 : "r"(laddr), "r"(rank));
    asm volatile("mbarrier.arrive.release.cluster.shared::cluster.b64 _, [%0];"
                 :: "r"(ra) : "memory");
}
__device__ __forceinline__ void mbar_wait(uint32_t addr, uint32_t parity) {
    asm volatile(
        "{\n\t.reg .pred P;\n\t"
        "W%=:\n\t"
        "mbarrier.try_wait.parity.acquire.cluster.shared::cta.b64 P, [%0], %1, 0x989680;\n\t"
        "@P bra D%=;\n\t"
        "bra W%=;\n\t"
        "D%=:\n\t}"
        :: "r"(addr), "r"(parity) : "memory");
}
__device__ __forceinline__ void barg(int gid) {
    asm volatile("bar.sync %0, %1;" :: "r"(gid + 1), "r"(320) : "memory");
}
#define CB() do { asm volatile("barrier.cluster.arrive.aligned;" ::: "memory"); \
                  asm volatile("barrier.cluster.wait.aligned;" ::: "memory"); } while (0)

// ===========================================================================
// k_pre (unchanged from R7)
// ===========================================================================
__global__ void __launch_bounds__(128) k_pre(const float* __restrict__ embed,
                                             const float* __restrict__ ctx,
                                             const float* __restrict__ actn,
                                             const float* __restrict__ w_obs,
                                             const float* __restrict__ b_obs,
                                             const float* __restrict__ w_inp,
                                             const float* __restrict__ b_inp) {
    __shared__ __align__(16) float As[16][140];
    const int tid = threadIdx.x;
    const int jp = tid & 31, rg = tid >> 5;

    if (blockIdx.x < 1024) {
        const int row0 = (blockIdx.x >> 2) * 128;
        const int j0 = (blockIdx.x & 3) * 64 + jp * 2;
        const bool act = (j0 < Hc);
        ull acc[32];
#pragma unroll
        for (int i = 0; i < 32; i++) acc[i] = 0ull;

        const int kkf = tid & 15, rbase0 = tid >> 4;
        for (int k0 = 0; k0 < Ec; k0 += 16) {
#pragma unroll
            for (int i = 0; i < 16; i++) {
                int r = rbase0 + i * 8;
                int rowg = row0 + r;
                int tt = rowg >> 9, bb = rowg & 511;
                As[kkf][r] = embed[(size_t)(bb * Tc + tt) * Ec + k0 + kkf];
            }
            __syncthreads();
            if (act) {
#pragma unroll 2
                for (int kk = 0; kk < 16; kk++) {
                    float2 w = *reinterpret_cast<const float2*>(
                        w_obs + (size_t)(Dc + k0 + kk) * Hc + j0);
                    ull wx = dup2(w.x), wy = dup2(w.y);
                    const ulonglong2* ap2 =
                        reinterpret_cast<const ulonglong2*>(&As[kk][rg * 32]);
#pragma unroll
                    for (int q = 0; q < 8; q++) {
                        ulonglong2 av = ap2[q];
                        fma2(acc[4 * q + 0], av.x, wx);
                        fma2(acc[4 * q + 1], av.x, wy);
                        fma2(acc[4 * q + 2], av.y, wx);
                        fma2(acc[4 * q + 3], av.y, wy);
                    }
                }
            }
            __syncthreads();
        }
        if (act) {
            float bx = b_obs[j0], by = b_obs[j0 + 1];
#pragma unroll
            for (int pq = 0; pq < 16; pq++) {
                float2 va = up2(acc[2 * pq]), vb = up2(acc[2 * pq + 1]);
                int r = row0 + rg * 32 + 2 * pq;
                *reinterpret_cast<float2*>(g_pre_obs + (size_t)r * Hc + j0) =
                    make_float2(va.x + bx, vb.x + by);
                *reinterpret_cast<float2*>(g_pre_obs + (size_t)(r + 1) * Hc + j0) =
                    make_float2(va.y + bx, vb.y + by);
            }
        }
    } else {
        const int bid = blockIdx.x - 1024;
        const int row0 = (bid >> 2) * 64;
        const int j0 = (bid & 3) * 64 + jp * 2;
        const bool act = (j0 < Hc);
        const int rbase = rg * 16;

        ull acc[16];
#pragma unroll
        for (int i = 0; i < 16; i++) acc[i] = 0ull;

        for (int k0 = 0; k0 < 272; k0 += 16) {
#pragma unroll
            for (int i = 0; i < 8; i++) {
                int lin = tid + i * 128;
                int kk = lin & 15, r = lin >> 4;
                int rowg = row0 + r;
                int tt = rowg >> 9, bb = rowg & 511;
                int k = k0 + kk;
                float v = 0.0f;
                if (k < SSc)            v = ctx[(size_t)(bb * Tc + tt) * SSc + k];
                else if (k < SSc + Ac)  v = actn[(size_t)(bb * Tc + tt) * Ac + (k - SSc)];
                As[kk][r] = v;
            }
            __syncthreads();
            if (act) {
#pragma unroll
                for (int kk = 0; kk < 16; kk++) {
                    int kw = (k0 + kk < SSc + Ac) ? (k0 + kk) : (SSc + Ac - 1);
                    float2 w = *reinterpret_cast<const float2*>(
                        w_inp + (size_t)(Sc + kw) * Hc + j0);
                    ull wx = dup2(w.x), wy = dup2(w.y);
                    const ull* ap = reinterpret_cast<const ull*>(&As[kk][rbase]);
#pragma unroll
                    for (int pq = 0; pq < 8; pq++) {
                        ull a = ap[pq];
                        fma2(acc[2 * pq], a, wx);
                        fma2(acc[2 * pq + 1], a, wy);
                    }
                }
            }
            __syncthreads();
        }
        if (act) {
            float bx = b_inp[j0], by = b_inp[j0 + 1];
#pragma unroll
            for (int pq = 0; pq < 8; pq++) {
                float2 va = up2(acc[2 * pq]), vb = up2(acc[2 * pq + 1]);
                int r = row0 + rbase + 2 * pq;
                *reinterpret_cast<float2*>(g_pre_inp + (size_t)r * Hc + j0) =
                    make_float2(va.x + bx, vb.x + by);
                *reinterpret_cast<float2*>(g_pre_inp + (size_t)(r + 1) * Hc + j0) =
                    make_float2(va.y + bx, vb.y + by);
            }
        }
    }
}

// ===========================================================================
// k_rssm v6 — per-group smem block (bytes, GS = 51584 per group):
//  XD   [400][4] ull  @     0 (12800)  x||d dup
//  DN   [200][4] ull  @ 12800 ( 6400)  deter_new dup (peer writes its cols)
//  HHO  [200][4] ull  @ 19200 ( 6400)  local h(100)||ho(100) dup
//  PART 2700 ull      @ 25600 (21600)  k-split partials, 9-ull stride
//  STP  [2][120][4] f @ 47200 ( 3840)  stat partials by source CTA
//  STF  [32][4] f     @ 51040 (  512)  stoch carry
// shared: BGRU@103168(2400) BIMG@105568(800) BIMS@106368(256) BOBS@106624(256)
//         MBAR@106880(32: per group {mb_dn, mb_st})     total 106912
// ===========================================================================
#define GS       51584
#define XD_O     0
#define DN_O     12800
#define HHO_O    19200
#define PART_O   25600
#define STP_O    47200
#define STF_O    51040
#define BGRU_OFF 103168
#define BIMG_OFF 105568
#define BIMS_OFF 106368
#define BOBS_OFF 106624
#define MBAR_OFF 106880
#define SMEM_BYTES 106912

__global__ void __launch_bounds__(640, 1) __cluster_dims__(2, 1, 1) k_rssm(
    const float* __restrict__ noise_p, const float* __restrict__ noise_o,
    const float* __restrict__ w_inp,  const float* __restrict__ w_gru,
    const float* __restrict__ b_gru_g,
    const float* __restrict__ w_img,  const float* __restrict__ b_img_g,
    const float* __restrict__ w_obsd,
    const float* __restrict__ w_ims,  const float* __restrict__ b_ims_g,
    const float* __restrict__ w_obst, const float* __restrict__ b_obst_g,
    float* __restrict__ out) {
    extern __shared__ __align__(16) char sm[];
    const int tid = threadIdx.x;
    const uint32_t p = ctarank();
    const uint32_t peer = 1u - p;
    const int b0 = (blockIdx.x >> 1) * 8;   // 8 rows per cluster
    const uint32_t base32 = smem_u32(sm);

    float* bgru = reinterpret_cast<float*>(sm + BGRU_OFF);
    float* bimg = reinterpret_cast<float*>(sm + BIMG_OFF);
    float* bims = reinterpret_cast<float*>(sm + BIMS_OFF);
    float* bobs = reinterpret_cast<float*>(sm + BOBS_OFF);

    // ---- init ----
    for (int i = tid; i < 600; i += 640) bgru[i] = b_gru_g[i];
    for (int i = tid; i < Hc; i += 640) bimg[i] = b_img_g[i];
    if (tid < 60) { bims[tid] = b_ims_g[tid]; bobs[tid] = b_obst_g[tid]; }
    for (int i = tid; i < 1600; i += 640) {          // d = 0 (both groups)
        int g2 = i / 800, idx = i % 800;
        reinterpret_cast<ull*>(sm + g2 * GS + XD_O)[800 + idx] = 0ull;
    }
    for (int i = tid; i < 256; i += 640) {           // stoch = 0 (both groups)
        int g2 = i / 128, idx = i % 128;
        reinterpret_cast<float*>(sm + g2 * GS + STF_O)[idx] = 0.0f;
    }
    if (tid == 0) {
        mbar_init(base32 + MBAR_OFF + 0, 100);   // g0 dn
        mbar_init(base32 + MBAR_OFF + 8, 120);   // g0 st
        mbar_init(base32 + MBAR_OFF + 16, 100);  // g1 dn
        mbar_init(base32 + MBAR_OFF + 24, 120);  // g1 st
    }
    __syncthreads();
    CB();

    // ---- group setup ----
    const int g = tid / 320;
    const int lt = tid - g * 320;
    const int rb = b0 + g * 4;              // this group's 4 global rows
    char* gb = sm + g * GS;
    ull*   xd_u  = reinterpret_cast<ull*>(gb + XD_O);
    ull*   dn_u  = reinterpret_cast<ull*>(gb + DN_O);
    ull*   hho_u = reinterpret_cast<ull*>(gb + HHO_O);
    ull*   pt_u  = reinterpret_cast<ull*>(gb + PART_O);
    float* pt_f  = reinterpret_cast<float*>(gb + PART_O);
    float* stpf  = reinterpret_cast<float*>(gb + STP_O);
    float* st_f  = reinterpret_cast<float*>(gb + STF_O);
    const ulonglong2* xd2  = reinterpret_cast<const ulonglong2*>(xd_u);
    const ulonglong2* dn2  = reinterpret_cast<const ulonglong2*>(dn_u);
    const ulonglong2* hho2 = reinterpret_cast<const ulonglong2*>(hho_u);
    const float* xd_f = reinterpret_cast<const float*>(xd_u);
    const float* dn_f = reinterpret_cast<const float*>(dn_u);
    const uint32_t mb_dn = base32 + MBAR_OFF + (uint32_t)g * 16;
    const uint32_t mb_st = mb_dn + 8;
    uint32_t ph = 0;

    for (int t = 0; t < Tc; t++) {
        // ---- P1: x = elu(stoch @ Wis + pre_inp[t]) for 4 rows ----
        if (lt < 200) {
            const int j = lt;
            const float* pi = g_pre_inp + ((size_t)t * Bc + rb) * Hc + j;
            float a0 = pi[0], a1 = pi[Hc], a2 = pi[2 * Hc], a3 = pi[3 * Hc];
#pragma unroll
            for (int k = 0; k < Sc; k++) {
                float w = w_inp[k * Hc + j];
                float4 s = *reinterpret_cast<const float4*>(&st_f[k * 4]);
                a0 = fmaf(w, s.x, a0); a1 = fmaf(w, s.y, a1);
                a2 = fmaf(w, s.z, a2); a3 = fmaf(w, s.w, a3);
            }
            ull* xo = &xd_u[j * 4];
            xo[0] = dup2(eluf(a0)); xo[1] = dup2(eluf(a1));
            xo[2] = dup2(eluf(a2)); xo[3] = dup2(eluf(a3));
        }
        barg(g);

        // ---- P2: GRU partials, our 300 gate-cols, k-split 4 (K=100) ----
        if (lt < 300) {
            const int cg = lt % 75, seg = lt / 75;
            const int lc = cg * 4;
            const int gate = lc / 100, jl = lc % 100;
            const int gcol0 = gate * 200 + (int)p * 100 + jl;
            const ulonglong2* Wp =
                reinterpret_cast<const ulonglong2*>(w_gru + gcol0) +
                (size_t)seg * 100 * 150;
            const ulonglong2* Ap = xd2 + (seg * 100) * 2;
            ull A0 = 0, A1 = 0, A2 = 0, A3 = 0, A4 = 0, A5 = 0, A6 = 0, A7 = 0;
#pragma unroll 4
            for (int kk = 0; kk < 100; kk++) {
                ulonglong2 w = Wp[(size_t)kk * 150];
                ulonglong2 a01 = Ap[kk * 2];
                ulonglong2 a23 = Ap[kk * 2 + 1];
                fma2(A0, a01.x, w.x); fma2(A1, a01.y, w.x);
                fma2(A2, a23.x, w.x); fma2(A3, a23.y, w.x);
                fma2(A4, a01.x, w.y); fma2(A5, a01.y, w.y);
                fma2(A6, a23.x, w.y); fma2(A7, a23.y, w.y);
            }
            ull* P = pt_u + (seg * 75 + cg) * 9;
            P[0] = A0; P[1] = A1; P[2] = A2; P[3] = A3;
            P[4] = A4; P[5] = A5; P[6] = A6; P[7] = A7;
        }
        barg(g);

        // ---- C2: combine -> deter_new (our 100 cols); dup local + peer ----
        if (lt < 100) {
            const int jl = lt;
            const int gd = (int)p * 100 + jl;
            const float bR = bgru[gd], bC = bgru[200 + gd], bU = bgru[400 + gd];
            // per-gate partial coordinates
            int cgg[3], cpg[3], eg[3];
#pragma unroll
            for (int gate = 0; gate < 3; gate++) {
                int lc = gate * 100 + jl;
                cgg[gate] = lc >> 2;
                int ci = lc & 3; cpg[gate] = ci >> 1; eg[gate] = ci & 1;
            }
#pragma unroll
            for (int r = 0; r < 4; r++) {
                float R = bR, C = bC, U = bU - 1.0f;
#pragma unroll
                for (int seg = 0; seg < 4; seg++) {
                    R += pt_f[(((seg * 75 + cgg[0]) * 9 + cpg[0] * 4 + r) << 1) + eg[0]];
                    C += pt_f[(((seg * 75 + cgg[1]) * 9 + cpg[1] * 4 + r) << 1) + eg[1]];
                    U += pt_f[(((seg * 75 + cgg[2]) * 9 + cpg[2] * 4 + r) << 1) + eg[2]];
                }
                float reset = sigm(R);
                float cand  = tanhf(reset * C);
                float upd   = sigm(U);
                float dprev = xd_f[((200 + gd) * 4 + r) * 2];
                float dnv = upd * cand + (1.0f - upd) * dprev;
                ull dv = dup2(dnv);
                dn_u[gd * 4 + r] = dv;
                st_peer_u64(base32 + (uint32_t)g * GS + DN_O +
                            (uint32_t)(gd * 4 + r) * 8, peer, dv);
            }
            mbar_arrive_peer(mb_dn, peer);
        }
        barg(g);
        mbar_wait(mb_dn, ph);

        // ---- P3: h/ho partials (our 100+100 cols, k-split 4) ∥ deter+carry ----
        if (lt < 200) {
            const int cg = lt % 50, seg = lt / 50;
            const float* W = (cg < 25)
                ? (w_img + (int)p * 100 + cg * 4)
                : (w_obsd + (int)p * 100 + (cg - 25) * 4);
            const ulonglong2* Wp = reinterpret_cast<const ulonglong2*>(W) +
                                   (size_t)(seg * 50) * 50;
            const ulonglong2* Ap = dn2 + (seg * 50) * 2;
            ull A0 = 0, A1 = 0, A2 = 0, A3 = 0, A4 = 0, A5 = 0, A6 = 0, A7 = 0;
#pragma unroll 5
            for (int kk = 0; kk < 50; kk++) {
                ulonglong2 w = Wp[(size_t)kk * 50];
                ulonglong2 a01 = Ap[kk * 2];
                ulonglong2 a23 = Ap[kk * 2 + 1];
                fma2(A0, a01.x, w.x); fma2(A1, a01.y, w.x);
                fma2(A2, a23.x, w.x); fma2(A3, a23.y, w.x);
                fma2(A4, a01.x, w.y); fma2(A5, a01.y, w.y);
                fma2(A6, a23.x, w.y); fma2(A7, a23.y, w.y);
            }
            ull* P = pt_u + (seg * 50 + cg) * 9;
            P[0] = A0; P[1] = A1; P[2] = A2; P[3] = A3;
            P[4] = A4; P[5] = A5; P[6] = A6; P[7] = A7;
        } else {
            const int tt2 = lt - 200;    // 0..119
            for (int i = tt2; i < 800; i += 120) {
                const int r = i / 200, j = i % 200;
                out[((size_t)(rb + r) * Tc + t) * OUTC + 180 + j] =
                    dn_f[(j * 4 + r) * 2];
            }
            for (int i = tt2; i < 800; i += 120)     // carry d <- deter_new
                xd_u[800 + i] = dn_u[i];
        }
        barg(g);

        // ---- C3: reduce + bias/pre_obs + elu -> local hho dup ----
        if (lt < 200) {
            const int cl = lt;
            const bool ish = cl < 100;
            const int jl = ish ? cl : cl - 100;
            const int gcol = (int)p * 100 + jl;
            const int cg = (ish ? 0 : 25) + (jl >> 2);
            const int ci = jl & 3, cp = ci >> 1, e = ci & 1;
            const float* po = g_pre_obs + ((size_t)t * Bc + rb) * Hc + gcol;
            const float bb = ish ? bimg[gcol] : 0.0f;
#pragma unroll
            for (int r = 0; r < 4; r++) {
                float v = ish ? bb : po[r * Hc];
#pragma unroll
                for (int seg = 0; seg < 4; seg++)
                    v += pt_f[(((seg * 50 + cg) * 9 + cp * 4 + r) << 1) + e];
                hho_u[cl * 4 + r] = dup2(eluf(v));
            }
        }
        barg(g);

        // ---- P4: stat partials over local 100-dim K slice (4 segs of 25) ----
        if (lt < 120) {
            const int grp = lt % 30, seg = lt / 30;
            const bool post = grp >= 15;
            const int ci4 = post ? grp - 15 : grp;
            const float* W = (post ? w_obst : w_ims) +
                             (size_t)((int)p * 100 + seg * 25) * 60 + ci4 * 4;
            const ulonglong2* Wp = reinterpret_cast<const ulonglong2*>(W);
            const ulonglong2* Ap = hho2 + ((post ? 100 : 0) + seg * 25) * 2;
            ull A0 = 0, A1 = 0, A2 = 0, A3 = 0, A4 = 0, A5 = 0, A6 = 0, A7 = 0;
#pragma unroll 5
            for (int kk = 0; kk < 25; kk++) {
                ulonglong2 w = Wp[(size_t)kk * 15];
                ulonglong2 a01 = Ap[kk * 2];
                ulonglong2 a23 = Ap[kk * 2 + 1];
                fma2(A0, a01.x, w.x); fma2(A1, a01.y, w.x);
                fma2(A2, a23.x, w.x); fma2(A3, a23.y, w.x);
                fma2(A4, a01.x, w.y); fma2(A5, a01.y, w.y);
                fma2(A6, a23.x, w.y); fma2(A7, a23.y, w.y);
            }
            ull* P = pt_u + (seg * 30 + grp) * 9;
            P[0] = A0; P[1] = A1; P[2] = A2; P[3] = A3;
            P[4] = A4; P[5] = A5; P[6] = A6; P[7] = A7;
        }
        barg(g);

        // ---- C4: reduce -> stat partial [120][4]; local slot + peer slot ----
        if (lt < 120) {
            const int c = lt;
            const bool post = c >= 60;
            const int cc = post ? c - 60 : c;
            const int grp = (post ? 15 : 0) + (cc >> 2);
            const int ci = cc & 3, cp = ci >> 1, e = ci & 1;
            float v[4];
#pragma unroll
            for (int r = 0; r < 4; r++) {
                float s = 0.0f;
#pragma unroll
                for (int seg = 0; seg < 4; seg++)
                    s += pt_f[(((seg * 30 + grp) * 9 + cp * 4 + r) << 1) + e];
                v[r] = s;
            }
            ull u0 = pk2(v[0], v[1]), u1 = pk2(v[2], v[3]);
            const uint32_t idx = (uint32_t)((int)p * 480 + c * 4);
            *reinterpret_cast<ull*>(stpf + idx) = u0;
            *reinterpret_cast<ull*>(stpf + idx + 2) = u1;
            st_peer_u64(base32 + (uint32_t)g * GS + STP_O + idx * 4, peer, u0);
            st_peer_u64(base32 + (uint32_t)g * GS + STP_O + idx * 4 + 8, peer, u1);
            mbar_arrive_peer(mb_st, peer);
        }
        barg(g);
        mbar_wait(mb_st, ph);

        // ---- P5: sample + outputs + carry ----
        if (lt < 120) {
            const int r = lt / 30, k = lt - r * 30;
            const int b = rb + r;
            float pm  = bims[k]      + stpf[k * 4 + r]        + stpf[480 + k * 4 + r];
            float psv = bims[30 + k] + stpf[(30 + k) * 4 + r] + stpf[480 + (30 + k) * 4 + r];
            float om  = bobs[k]      + stpf[(60 + k) * 4 + r] + stpf[480 + (60 + k) * 4 + r];
            float osv = bobs[30 + k] + stpf[(90 + k) * 4 + r] + stpf[480 + (90 + k) * 4 + r];
            psv = softplusf(psv) + 0.1f;
            osv = softplusf(osv) + 0.1f;
            float ost = fmaf(osv, noise_o[((size_t)t * Bc + b) * Sc + k], om);
            float pst = fmaf(psv, noise_p[((size_t)t * Bc + b) * Sc + k], pm);
            st_f[k * 4 + r] = ost;
            if ((k < 15) == (p == 0)) {
                size_t basep = ((size_t)b * Tc + t) * OUTC;
                out[basep + k]       = om;
                out[basep + 30 + k]  = osv;
                out[basep + 60 + k]  = ost;
                out[basep + 90 + k]  = pm;
                out[basep + 120 + k] = psv;
                out[basep + 150 + k] = pst;
            }
        }
        barg(g);
        ph ^= 1;
    }
    CB();
}

// ===========================================================================
extern "C" void kernel_launch(void* const* d_in, const int* in_sizes, int n_in,
                              void* d_out, int out_size) {
    const float* embed       = (const float*)d_in[0];
    const float* action      = (const float*)d_in[1];
    const float* context     = (const float*)d_in[2];
    const float* noise_prior = (const float*)d_in[3];
    const float* noise_post  = (const float*)d_in[4];
    const float* w_inp       = (const float*)d_in[5];
    const float* b_inp       = (const float*)d_in[6];
    const float* w_gru       = (const float*)d_in[7];
    const float* b_gru       = (const float*)d_in[8];
    const float* w_img_out   = (const float*)d_in[9];
    const float* b_img_out   = (const float*)d_in[10];
    const float* w_obs_out   = (const float*)d_in[11];
    const float* b_obs_out   = (const float*)d_in[12];
    const float* w_ims_stat  = (const float*)d_in[13];
    const float* b_ims_stat  = (const float*)d_in[14];
    const float* w_obs_stat  = (const float*)d_in[15];
    const float* b_obs_stat  = (const float*)d_in[16];
    float* out = (float*)d_out;

    static int smem_set = 0;
    if (!smem_set) {
        cudaFuncSetAttribute(k_rssm, cudaFuncAttributeMaxDynamicSharedMemorySize,
                             SMEM_BYTES);
        smem_set = 1;
    }

    k_pre<<<3072, 128>>>(embed, context, action, w_obs_out, b_obs_out,
                         w_inp, b_inp);
    k_rssm<<<128, 640, SMEM_BYTES>>>(noise_prior, noise_post, w_inp, w_gru,
                                     b_gru, w_img_out, b_img_out, w_obs_out,
                                     w_ims_stat, b_ims_stat, w_obs_stat,
                                     b_obs_stat, out);
}

// round 10
// speedup vs baseline: 1.3464x; 1.3464x over previous
#include <cuda_runtime.h>
#include <cuda_bf16.h>
#include <cstdint>

// ---------------------------------------------------------------------------
// RSSM observe scan, GB300 — round 10.
//   k_pre_inp     : fp32 (R3-proven).
//   k_pre_obs_mma : split-bf16 (3-term) GEMM 32768x200x1024 via warp-level
//                   mma.sync.m16n8k16 (compute_103-legal; tcgen05 is NOT —
//                   harness targets compute_103 without the 'a' feature set).
//   k_rssm        : exact R6 v4 (proven best scan).
// ---------------------------------------------------------------------------

#define Bc 512
#define Tc 64
#define Ec 1024
#define Ac 32
#define Sc 30
#define Dc 200
#define Hc 200
#define SSc 230
#define OUTC 380

typedef unsigned long long ull;

__device__ float g_pre_inp[Tc * Bc * Hc];
__device__ float g_pre_obs[Tc * Bc * Hc];

// ---- packed f32x2 helpers -------------------------------------------------
__device__ __forceinline__ ull pk2(float a, float b) {
    ull r; asm("mov.b64 %0, {%1, %2};" : "=l"(r) : "f"(a), "f"(b)); return r;
}
__device__ __forceinline__ ull dup2(float a) {
    ull r; asm("mov.b64 %0, {%1, %1};" : "=l"(r) : "f"(a)); return r;
}
__device__ __forceinline__ float2 up2(ull v) {
    float x, y; asm("mov.b64 {%0, %1}, %2;" : "=f"(x), "=f"(y) : "l"(v));
    return make_float2(x, y);
}
__device__ __forceinline__ void fma2(ull& acc, ull a, ull b) {
    asm("fma.rn.f32x2 %0, %1, %2, %0;" : "+l"(acc) : "l"(a), "l"(b));
}

__device__ __forceinline__ float sigm(float x) { return 1.0f / (1.0f + __expf(-x)); }
__device__ __forceinline__ float eluf(float x) { return x > 0.0f ? x : (__expf(x) - 1.0f); }
__device__ __forceinline__ float softplusf(float x) {
    return x > 15.0f ? x : log1pf(__expf(x));
}

// ---- cluster / smem helpers -------------------------------------------------
__device__ __forceinline__ uint32_t smem_u32(const void* p) {
    uint32_t a;
    asm("{ .reg .u64 t; cvta.to.shared.u64 t, %1; cvt.u32.u64 %0, t; }"
        : "=r"(a) : "l"(p));
    return a;
}
__device__ __forceinline__ void st_peer_u64(uint32_t laddr, uint32_t rank, ull v) {
    uint32_t ra;
    asm volatile("mapa.shared::cluster.u32 %0, %1, %2;" : "=r"(ra)
                 : "r"(laddr), "r"(rank));
    asm volatile("st.shared::cluster.u64 [%0], %1;" :: "r"(ra), "l"(v) : "memory");
}
__device__ __forceinline__ void st_peer_f32(uint32_t laddr, uint32_t rank, float v) {
    uint32_t ra;
    asm volatile("mapa.shared::cluster.u32 %0, %1, %2;" : "=r"(ra)
                 : "r"(laddr), "r"(rank));
    asm volatile("st.shared::cluster.f32 [%0], %1;" :: "r"(ra), "f"(v) : "memory");
}
__device__ __forceinline__ uint32_t ctarank() {
    uint32_t r; asm("mov.u32 %0, %%cluster_ctarank;" : "=r"(r)); return r;
}
#define CB() do { asm volatile("barrier.cluster.arrive.aligned;" ::: "memory"); \
                  asm volatile("barrier.cluster.wait.aligned;" ::: "memory"); } while (0)

// ---- mma.sync helpers (compute_103-legal) -----------------------------------
__device__ __forceinline__ void ldmx4(uint32_t* a, uint32_t addr) {
    asm volatile("ldmatrix.sync.aligned.m8n8.x4.shared.b16 {%0,%1,%2,%3}, [%4];"
                 : "=r"(a[0]), "=r"(a[1]), "=r"(a[2]), "=r"(a[3]) : "r"(addr));
}
__device__ __forceinline__ void ldmx2(uint32_t* a, uint32_t addr) {
    asm volatile("ldmatrix.sync.aligned.m8n8.x2.shared.b16 {%0,%1}, [%2];"
                 : "=r"(a[0]), "=r"(a[1]) : "r"(addr));
}
__device__ __forceinline__ void mma16816(float* c, const uint32_t* a,
                                         const uint32_t* b) {
    asm volatile(
        "mma.sync.aligned.m16n8k16.row.col.f32.bf16.bf16.f32 "
        "{%0,%1,%2,%3},{%4,%5,%6,%7},{%8,%9},{%0,%1,%2,%3};"
        : "+f"(c[0]), "+f"(c[1]), "+f"(c[2]), "+f"(c[3])
        : "r"(a[0]), "r"(a[1]), "r"(a[2]), "r"(a[3]), "r"(b[0]), "r"(b[1]));
}

// ===========================================================================
// k_pre_obs_mma: g_pre_obs = embed @ w_obs[200:1224] + b_obs
// split-bf16: D = Ah*Bh + Al*Bh + Ah*Bl. 256 CTAs x 512 thr.
// CTA tile M=128, N=200 (25 n8-tiles), K chunks of 16.
// Warp w: m-tile = w>>1 (16 rows), n-half = w&1 (13 / 12 n-tiles).
// smem tiles: row stride 24 bf16 (48B) -> conflict-free ldmatrix.
// ===========================================================================
__global__ void __launch_bounds__(512, 1)
k_pre_obs_mma(const float* __restrict__ embed,
              const float* __restrict__ w_obs,
              const float* __restrict__ b_obs) {
    __shared__ __align__(16) __nv_bfloat16 sAhi[128 * 24];
    __shared__ __align__(16) __nv_bfloat16 sAlo[128 * 24];
    __shared__ __align__(16) __nv_bfloat16 sBhi[200 * 24];
    __shared__ __align__(16) __nv_bfloat16 sBlo[200 * 24];
    __shared__ float sbias[200];

    const int tid = threadIdx.x;
    const int wid = tid >> 5, lane = tid & 31;
    const int row0 = blockIdx.x * 128;

    // staging assignments
    const int ar = tid >> 2;                 // A: row 0..127
    const int akq = (tid & 3) * 4;           // A: k quad within 16
    const int arg = row0 + ar;
    const float* aSrc =
        embed + ((size_t)((arg & 511) * Tc + (arg >> 9))) * Ec + akq;
    int bk[7], bn[7];
#pragma unroll
    for (int j = 0; j < 7; j++) {
        int idx = tid + j * 512;
        bk[j] = idx / 200; bn[j] = idx - bk[j] * 200;   // idx<3200 guard at use
    }

    for (int i = tid; i < Hc; i += 512) sbias[i] = b_obs[i];

    // warp tiling
    const int mtile = wid >> 1;
    const int ntb = (wid & 1) * 13;
    const int ncnt = (wid & 1) ? 12 : 13;
    const uint32_t aoff =
        (uint32_t)(((mtile * 16 + (lane & 15)) * 24 + (lane >> 4) * 8) * 2);
    const uint32_t aHiAddr = smem_u32(sAhi) + aoff;
    const uint32_t aLoAddr = smem_u32(sAlo) + aoff;
    const uint32_t boff =
        (uint32_t)((((lane & 7)) * 24 + ((lane >> 3) & 1) * 8) * 2);
    const uint32_t bHiBase = smem_u32(sBhi) + boff + (uint32_t)(ntb * 8 * 48);
    const uint32_t bLoBase = smem_u32(sBlo) + boff + (uint32_t)(ntb * 8 * 48);

    float acc[13][4];
#pragma unroll
    for (int q = 0; q < 13; q++)
#pragma unroll
        for (int i = 0; i < 4; i++) acc[q][i] = 0.0f;

    // prologue: load chunk 0
    float araw[4], braw[7];
    {
        float4 v = *reinterpret_cast<const float4*>(aSrc);
        araw[0] = v.x; araw[1] = v.y; araw[2] = v.z; araw[3] = v.w;
#pragma unroll
        for (int j = 0; j < 7; j++)
            if (tid + j * 512 < 3200)
                braw[j] = w_obs[(size_t)(Dc + bk[j]) * Hc + bn[j]];
    }

    for (int ck = 0; ck < 64; ck++) {
        // ---- cvt + store staged chunk ----
        {
            __nv_bfloat16* ah = sAhi + ar * 24 + akq;
            __nv_bfloat16* al = sAlo + ar * 24 + akq;
#pragma unroll
            for (int i = 0; i < 4; i++) {
                __nv_bfloat16 h = __float2bfloat16(araw[i]);
                ah[i] = h;
                al[i] = __float2bfloat16(araw[i] - __bfloat162float(h));
            }
#pragma unroll
            for (int j = 0; j < 7; j++) {
                if (tid + j * 512 < 3200) {
                    __nv_bfloat16 h = __float2bfloat16(braw[j]);
                    sBhi[bn[j] * 24 + bk[j]] = h;
                    sBlo[bn[j] * 24 + bk[j]] =
                        __float2bfloat16(braw[j] - __bfloat162float(h));
                }
            }
        }
        __syncthreads();

        // ---- prefetch next chunk into regs (overlaps MMA below) ----
        if (ck < 63) {
            const int k0n = (ck + 1) * 16;
            float4 v = *reinterpret_cast<const float4*>(aSrc + k0n);
            araw[0] = v.x; araw[1] = v.y; araw[2] = v.z; araw[3] = v.w;
#pragma unroll
            for (int j = 0; j < 7; j++)
                if (tid + j * 512 < 3200)
                    braw[j] = w_obs[(size_t)(Dc + k0n + bk[j]) * Hc + bn[j]];
        }

        // ---- ldmatrix + mma ----
        {
            uint32_t ah[4], al[4];
            ldmx4(ah, aHiAddr);
            ldmx4(al, aLoAddr);
#pragma unroll
            for (int q = 0; q < 13; q++) {
                if (q < ncnt) {
                    uint32_t bh[2], bl[2];
                    ldmx2(bh, bHiBase + (uint32_t)q * 384);
                    ldmx2(bl, bLoBase + (uint32_t)q * 384);
                    mma16816(acc[q], ah, bh);
                    mma16816(acc[q], al, bh);
                    mma16816(acc[q], ah, bl);
                }
            }
        }
        __syncthreads();
    }

    // ---- epilogue: acc -> +bias -> g_pre_obs ----
    {
        const int gq = lane >> 2, t4 = lane & 3;
        const int m0 = row0 + mtile * 16 + gq;
#pragma unroll
        for (int q = 0; q < 13; q++) {
            if (q < ncnt) {
                const int n = (ntb + q) * 8 + 2 * t4;
                const float b0 = sbias[n], b1 = sbias[n + 1];
                *reinterpret_cast<float2*>(g_pre_obs + (size_t)m0 * Hc + n) =
                    make_float2(acc[q][0] + b0, acc[q][1] + b1);
                *reinterpret_cast<float2*>(g_pre_obs + (size_t)(m0 + 8) * Hc + n) =
                    make_float2(acc[q][2] + b0, acc[q][3] + b1);
            }
        }
    }
}

// ===========================================================================
// k_pre_inp: fp32, R3-proven variant
// ===========================================================================
__global__ void __launch_bounds__(128) k_pre_inp(const float* __restrict__ ctx,
                                                 const float* __restrict__ actn,
                                                 const float* __restrict__ w_inp,
                                                 const float* __restrict__ b_inp) {
    __shared__ __align__(8) float As[16][66];
    const int tid = threadIdx.x;
    const int jp = tid & 31, rg = tid >> 5;
    const int row0 = blockIdx.x * 64;
    const int j0 = blockIdx.y * 64 + jp * 2;
    const bool act = (j0 < Hc);
    const int rbase = rg * 16;

    ull acc[16];
#pragma unroll
    for (int i = 0; i < 16; i++) acc[i] = 0ull;

    for (int k0 = 0; k0 < 272; k0 += 16) {
#pragma unroll
        for (int i = 0; i < 8; i++) {
            int lin = tid + i * 128;
            int kk = lin & 15, r = lin >> 4;
            int rowg = row0 + r;
            int tt = rowg >> 9, bb = rowg & 511;
            int k = k0 + kk;
            float v = 0.0f;
            if (k < SSc)            v = ctx[(size_t)(bb * Tc + tt) * SSc + k];
            else if (k < SSc + Ac)  v = actn[(size_t)(bb * Tc + tt) * Ac + (k - SSc)];
            As[kk][r] = v;
        }
        __syncthreads();
        if (act) {
#pragma unroll
            for (int kk = 0; kk < 16; kk++) {
                int kw = (k0 + kk < SSc + Ac) ? (k0 + kk) : (SSc + Ac - 1);
                float2 w = *reinterpret_cast<const float2*>(
                    w_inp + (size_t)(Sc + kw) * Hc + j0);
                ull wx = dup2(w.x), wy = dup2(w.y);
                const ull* ap = reinterpret_cast<const ull*>(&As[kk][rbase]);
#pragma unroll
                for (int pq = 0; pq < 8; pq++) {
                    ull a = ap[pq];
                    fma2(acc[2 * pq], a, wx);
                    fma2(acc[2 * pq + 1], a, wy);
                }
            }
        }
        __syncthreads();
    }
    if (act) {
        float bx = b_inp[j0], by = b_inp[j0 + 1];
#pragma unroll
        for (int pq = 0; pq < 8; pq++) {
            float2 va = up2(acc[2 * pq]), vb = up2(acc[2 * pq + 1]);
            int r = row0 + rbase + 2 * pq;
            *reinterpret_cast<float2*>(g_pre_inp + (size_t)r * Hc + j0) =
                make_float2(va.x + bx, vb.x + by);
            *reinterpret_cast<float2*>(g_pre_inp + (size_t)(r + 1) * Hc + j0) =
                make_float2(va.y + bx, vb.y + by);
        }
    }
}

// ===========================================================================
// k_rssm — exact R6 v4 (proven best scan)
// ===========================================================================
#define XD_OFF   0
#define DN_OFF   25600
#define HHO_OFF  38400
#define PART_OFF 64000
#define STS_OFF  104800
#define SOS_OFF  106848
#define STF_OFF  108896
#define BGRU_OFF 109920
#define BIMG_OFF 112320
#define BIMS_OFF 113120
#define BOBS_OFF 113376
#define SMEM_BYTES 113632

__global__ void __launch_bounds__(640, 1) __cluster_dims__(2, 1, 1) k_rssm(
    const float* __restrict__ noise_p, const float* __restrict__ noise_o,
    const float* __restrict__ w_inp,  const float* __restrict__ w_gru,
    const float* __restrict__ b_gru_g,
    const float* __restrict__ w_img,  const float* __restrict__ b_img_g,
    const float* __restrict__ w_obsd,
    const float* __restrict__ w_ims,  const float* __restrict__ b_ims_g,
    const float* __restrict__ w_obst, const float* __restrict__ b_obst_g,
    float* __restrict__ out) {
    extern __shared__ __align__(16) char sm[];
    ull*   xd_u   = reinterpret_cast<ull*>(sm + XD_OFF);
    ull*   dn_u   = reinterpret_cast<ull*>(sm + DN_OFF);
    ull*   hho_u  = reinterpret_cast<ull*>(sm + HHO_OFF);
    ull*   part_u = reinterpret_cast<ull*>(sm + PART_OFF);
    float* part_f = reinterpret_cast<float*>(sm + PART_OFF);
    float* stS    = reinterpret_cast<float*>(sm + STS_OFF);
    float* soS    = reinterpret_cast<float*>(sm + SOS_OFF);
    float* st_f   = reinterpret_cast<float*>(sm + STF_OFF);
    float* bgru   = reinterpret_cast<float*>(sm + BGRU_OFF);
    float* bimg   = reinterpret_cast<float*>(sm + BIMG_OFF);
    float* bims   = reinterpret_cast<float*>(sm + BIMS_OFF);
    float* bobs   = reinterpret_cast<float*>(sm + BOBS_OFF);
    const ulonglong2* xd_u2 = reinterpret_cast<const ulonglong2*>(xd_u);
    const ulonglong2* dn_u2 = reinterpret_cast<const ulonglong2*>(dn_u);
    const ulonglong2* hho_u2 = reinterpret_cast<const ulonglong2*>(hho_u);
    const float* xd_f = reinterpret_cast<const float*>(xd_u);
    const float* dn_f = reinterpret_cast<const float*>(dn_u);

    const int tid = threadIdx.x;
    const uint32_t p = ctarank();
    const uint32_t peer = 1u - p;
    const int b0 = (blockIdx.x >> 1) * 8;
    const uint32_t base32 = smem_u32(sm);

    for (int i = tid; i < 600; i += 640) bgru[i] = b_gru_g[i];
    for (int i = tid; i < Hc; i += 640) bimg[i] = b_img_g[i];
    if (tid < 60) { bims[tid] = b_ims_g[tid]; bobs[tid] = b_obst_g[tid]; }
    for (int i = tid; i < 1600; i += 640) xd_u[1600 + i] = 0ull;
    for (int i = tid; i < 256; i += 640) st_f[i] = 0.0f;
    __syncthreads();
    CB();

    for (int t = 0; t < Tc; t++) {
        if (tid < 400) {
            const int j = tid >> 1, rh = tid & 1;
            const float* pi = g_pre_inp + ((size_t)t * Bc + b0) * Hc + j;
            float a0 = pi[(rh * 4 + 0) * Hc], a1 = pi[(rh * 4 + 1) * Hc];
            float a2 = pi[(rh * 4 + 2) * Hc], a3 = pi[(rh * 4 + 3) * Hc];
#pragma unroll
            for (int k = 0; k < Sc; k++) {
                float w = w_inp[k * Hc + j];
                float4 s = *reinterpret_cast<const float4*>(&st_f[k * 8 + rh * 4]);
                a0 = fmaf(w, s.x, a0); a1 = fmaf(w, s.y, a1);
                a2 = fmaf(w, s.z, a2); a3 = fmaf(w, s.w, a3);
            }
            ull* xo = &xd_u[j * 8 + rh * 4];
            xo[0] = dup2(eluf(a0)); xo[1] = dup2(eluf(a1));
            xo[2] = dup2(eluf(a2)); xo[3] = dup2(eluf(a3));
        }
        __syncthreads();

        if (tid < 600) {
            const int cg = tid % 75;
            const int z = tid / 75;
            const int rh = z & 1, seg = z >> 1;
            const int lc0 = cg * 4;
            const int gcol0 = (lc0 / 100) * 200 + (int)p * 100 + (lc0 % 100);
            const ulonglong2* Wp = reinterpret_cast<const ulonglong2*>(w_gru + gcol0)
                                   + (size_t)seg * 100 * 150;
            const ulonglong2* Ap = xd_u2 + (seg * 100) * 4 + rh * 2;
            ull A0 = 0, A1 = 0, A2 = 0, A3 = 0, A4 = 0, A5 = 0, A6 = 0, A7 = 0;
#pragma unroll 4
            for (int kk = 0; kk < 100; kk++) {
                ulonglong2 w = Wp[(size_t)kk * 150];
                ulonglong2 a01 = Ap[kk * 4];
                ulonglong2 a23 = Ap[kk * 4 + 1];
                fma2(A0, w.x, a01.x); fma2(A1, w.y, a01.x);
                fma2(A2, w.x, a01.y); fma2(A3, w.y, a01.y);
                fma2(A4, w.x, a23.x); fma2(A5, w.y, a23.x);
                fma2(A6, w.x, a23.y); fma2(A7, w.y, a23.y);
            }
            ull* P = part_u + (seg * 75 + cg) * 17 + rh * 4;
            P[0] = A0; P[8] = A1; P[1] = A2; P[9] = A3;
            P[2] = A4; P[10] = A5; P[3] = A6; P[11] = A7;
        }
        __syncthreads();

        if (tid < 400) {
            const int j = tid >> 2, q = tid & 3;
            const int gd = (int)p * 100 + j;
            const int jq = j >> 2, ci = j & 3, cp = ci >> 1, e = ci & 1;
            const float bR = bgru[gd], bC = bgru[200 + gd], bU = bgru[400 + gd];
#pragma unroll
            for (int w2 = 0; w2 < 2; w2++) {
                const int rr = q * 2 + w2;
                float R = bR, C = bC, U = bU - 1.0f;
#pragma unroll
                for (int seg = 0; seg < 4; seg++) {
                    R += part_f[(((seg * 75 + 0 * 25 + jq) * 17 + cp * 8 + rr) << 1) + e];
                    C += part_f[(((seg * 75 + 1 * 25 + jq) * 17 + cp * 8 + rr) << 1) + e];
                    U += part_f[(((seg * 75 + 2 * 25 + jq) * 17 + cp * 8 + rr) << 1) + e];
                }
                float reset = sigm(R);
                float cand  = tanhf(reset * C);
                float upd   = sigm(U);
                float dprev = xd_f[((200 + gd) * 8 + rr) * 2];
                float dnv = upd * cand + (1.0f - upd) * dprev;
                ull dv = dup2(dnv);
                dn_u[gd * 8 + rr] = dv;
                st_peer_u64(base32 + DN_OFF + (uint32_t)(gd * 8 + rr) * 8, peer, dv);
            }
        }
        CB();

        if (tid < 400) {
            const int grp = tid % 50;
            const int z = tid / 50;
            const int rh = z & 1, seg = z >> 1;
            const float* W = (grp < 25)
                ? (w_img + (int)p * 100 + grp * 4)
                : (w_obsd + (int)p * 100 + (grp - 25) * 4);
            const ulonglong2* Wp = reinterpret_cast<const ulonglong2*>(W)
                                   + (size_t)(seg * 50) * 50;
            const ulonglong2* Ap = dn_u2 + (seg * 50) * 4 + rh * 2;
            ull A0 = 0, A1 = 0, A2 = 0, A3 = 0, A4 = 0, A5 = 0, A6 = 0, A7 = 0;
#pragma unroll 5
            for (int kk = 0; kk < 50; kk++) {
                ulonglong2 w = Wp[(size_t)kk * 50];
                ulonglong2 a01 = Ap[kk * 4];
                ulonglong2 a23 = Ap[kk * 4 + 1];
                fma2(A0, w.x, a01.x); fma2(A1, w.y, a01.x);
                fma2(A2, w.x, a01.y); fma2(A3, w.y, a01.y);
                fma2(A4, w.x, a23.x); fma2(A5, w.y, a23.x);
                fma2(A6, w.x, a23.y); fma2(A7, w.y, a23.y);
            }
            ull* P = part_u + (seg * 50 + grp) * 17 + rh * 4;
            P[0] = A0; P[8] = A1; P[1] = A2; P[9] = A3;
            P[2] = A4; P[10] = A5; P[3] = A6; P[11] = A7;
        } else {
            const int tt2 = tid - 400;
            for (int i = tt2; i < 800; i += 240) {
                const int rl = i / 200, j = i % 200;
                const int r = (int)p * 4 + rl;
                out[((size_t)(b0 + r) * Tc + t) * OUTC + 180 + j] =
                    dn_f[(j * 8 + r) * 2];
            }
            for (int i = tt2; i < 1600; i += 240) xd_u[1600 + i] = dn_u[i];
        }
        __syncthreads();

        if (tid < 400) {
            const int cl = tid >> 1;
            const int rh = (tid & 1) * 4;
            const bool ish = cl < 100;
            const int gcol = (int)p * 100 + (ish ? cl : cl - 100);
            const int grp = ish ? (cl >> 2) : (25 + ((cl - 100) >> 2));
            const int ci = cl & 3, cp = ci >> 1, e = ci & 1;
            const float* po = g_pre_obs + ((size_t)t * Bc + b0) * Hc + gcol;
            const float bb = ish ? bimg[gcol] : 0.0f;
            const int dsti = ish ? gcol : 200 + gcol;
#pragma unroll
            for (int i = 0; i < 4; i++) {
                const int r = rh + i;
                float v = ish ? bb : po[r * Hc];
#pragma unroll
                for (int seg = 0; seg < 4; seg++)
                    v += part_f[(((seg * 50 + grp) * 17 + cp * 8 + r) << 1) + e];
                ull dv = dup2(eluf(v));
                hho_u[dsti * 8 + r] = dv;
                st_peer_u64(base32 + HHO_OFF + (uint32_t)(dsti * 8 + r) * 8, peer, dv);
            }
        }
        CB();

        if (tid < 240) {
            const int grp = tid % 15;
            const int z = tid / 15;
            const int rh = z & 1, seg = z >> 1;
            const float* W = (p ? w_obst : w_ims) + grp * 4;
            const ulonglong2* Wp = reinterpret_cast<const ulonglong2*>(W)
                                   + (size_t)(seg * 25) * 15;
            const ulonglong2* Ap = hho_u2 + (int)p * 800 + (seg * 25) * 4 + rh * 2;
            ull A0 = 0, A1 = 0, A2 = 0, A3 = 0, A4 = 0, A5 = 0, A6 = 0, A7 = 0;
#pragma unroll 5
            for (int kk = 0; kk < 25; kk++) {
                ulonglong2 w = Wp[(size_t)kk * 15];
                ulonglong2 a01 = Ap[kk * 4];
                ulonglong2 a23 = Ap[kk * 4 + 1];
                fma2(A0, w.x, a01.x); fma2(A1, w.y, a01.x);
                fma2(A2, w.x, a01.y); fma2(A3, w.y, a01.y);
                fma2(A4, w.x, a23.x); fma2(A5, w.y, a23.x);
                fma2(A6, w.x, a23.y); fma2(A7, w.y, a23.y);
            }
            ull* P = part_u + (seg * 15 + grp) * 17 + rh * 4;
            P[0] = A0; P[8] = A1; P[1] = A2; P[9] = A3;
            P[2] = A4; P[10] = A5; P[3] = A6; P[11] = A7;
        }
        __syncthreads();

        if (tid < 240) {
            const int col = tid >> 2, q = tid & 3;
            const int cgq = col >> 2, ci = col & 3, cp = ci >> 1, e = ci & 1;
            const float bb = p ? bobs[col] : bims[col];
            const uint32_t dstoff = p ? SOS_OFF : STS_OFF;
            float* dst = reinterpret_cast<float*>(sm + dstoff);
#pragma unroll
            for (int w2 = 0; w2 < 2; w2++) {
                const int rr = q * 2 + w2;
                float v = bb;
#pragma unroll
                for (int seg = 0; seg < 8; seg++)
                    v += part_f[(((seg * 15 + cgq) * 17 + cp * 8 + rr) << 1) + e];
                dst[rr * 64 + col] = v;
                st_peer_f32(base32 + dstoff + (uint32_t)(rr * 64 + col) * 4, peer, v);
            }
        }
        CB();

        if (tid < 240) {
            const int r = tid / 30, k = tid - r * 30;
            const int b = b0 + r;
            float om  = soS[r * 64 + k];
            float osv = softplusf(soS[r * 64 + 30 + k]) + 0.1f;
            float ost = fmaf(osv, noise_o[((size_t)t * Bc + b) * Sc + k], om);
            st_f[k * 8 + r] = ost;
            if ((r >> 2) == (int)p) {
                float pm  = stS[r * 64 + k];
                float psv = softplusf(stS[r * 64 + 30 + k]) + 0.1f;
                float pst = fmaf(psv, noise_p[((size_t)t * Bc + b) * Sc + k], pm);
                size_t basep = ((size_t)b * Tc + t) * OUTC;
                out[basep + k]       = om;
                out[basep + 30 + k]  = osv;
                out[basep + 60 + k]  = ost;
                out[basep + 90 + k]  = pm;
                out[basep + 120 + k] = psv;
                out[basep + 150 + k] = pst;
            }
        }
        __syncthreads();
    }
}

// ===========================================================================
extern "C" void kernel_launch(void* const* d_in, const int* in_sizes, int n_in,
                              void* d_out, int out_size) {
    const float* embed       = (const float*)d_in[0];
    const float* action      = (const float*)d_in[1];
    const float* context     = (const float*)d_in[2];
    const float* noise_prior = (const float*)d_in[3];
    const float* noise_post  = (const float*)d_in[4];
    const float* w_inp       = (const float*)d_in[5];
    const float* b_inp       = (const float*)d_in[6];
    const float* w_gru       = (const float*)d_in[7];
    const float* b_gru       = (const float*)d_in[8];
    const float* w_img_out   = (const float*)d_in[9];
    const float* b_img_out   = (const float*)d_in[10];
    const float* w_obs_out   = (const float*)d_in[11];
    const float* b_obs_out   = (const float*)d_in[12];
    const float* w_ims_stat  = (const float*)d_in[13];
    const float* b_ims_stat  = (const float*)d_in[14];
    const float* w_obs_stat  = (const float*)d_in[15];
    const float* b_obs_stat  = (const float*)d_in[16];
    float* out = (float*)d_out;

    static int smem_set = 0;
    if (!smem_set) {
        cudaFuncSetAttribute(k_rssm, cudaFuncAttributeMaxDynamicSharedMemorySize,
                             SMEM_BYTES);
        smem_set = 1;
    }

    k_pre_inp<<<dim3(Bc * Tc / 64, 4), 128>>>(context, action, w_inp, b_inp);
    k_pre_obs_mma<<<Bc * Tc / 128, 512>>>(embed, w_obs_out, b_obs_out);
    k_rssm<<<128, 640, SMEM_BYTES>>>(noise_prior, noise_post, w_inp, w_gru,
                                     b_gru, w_img_out, b_img_out, w_obs_out,
                                     w_ims_stat, b_ims_stat, w_obs_stat,
                                     b_obs_stat, out);
}